// round 1
// baseline (speedup 1.0000x reference)
#include <cuda_runtime.h>
#include <cstdint>

// ---------------------------------------------------------------------------
// Problem constants
// ---------------------------------------------------------------------------
#define NTOK   4096
#define HID    1152
#define NHEAD  16
#define HDIM   72
#define HALF   36
#define QUART  18

// ---------------------------------------------------------------------------
// Packed f32x2 helpers (sm_103a FFMA2 path — 2x fp32 throughput vs FFMA)
// ---------------------------------------------------------------------------
typedef unsigned long long f32x2;

__device__ __forceinline__ f32x2 ffma2(f32x2 a, f32x2 b, f32x2 c) {
    f32x2 d;
    asm("fma.rn.f32x2 %0, %1, %2, %3;" : "=l"(d) : "l"(a), "l"(b), "l"(c));
    return d;
}
__device__ __forceinline__ f32x2 fmul2(f32x2 a, f32x2 b) {
    f32x2 d;
    asm("mul.rn.f32x2 %0, %1, %2;" : "=l"(d) : "l"(a), "l"(b));
    return d;
}
__device__ __forceinline__ f32x2 pack2(float lo, float hi) {
    f32x2 d;
    asm("mov.b64 %0, {%1, %2};" : "=l"(d) : "f"(lo), "f"(hi));
    return d;
}
__device__ __forceinline__ void unpack2(f32x2 v, float& lo, float& hi) {
    asm("mov.b64 {%0, %1}, %2;" : "=f"(lo), "=f"(hi) : "l"(v));
}

// ---------------------------------------------------------------------------
// Scratch (no cudaMalloc allowed) : Q, K, V, O buffers  (4 x 18.9 MB)
// ---------------------------------------------------------------------------
__device__ float g_bufQ[NTOK * HID];
__device__ float g_bufK[NTOK * HID];
__device__ float g_bufV[NTOK * HID];
__device__ float g_bufO[NTOK * HID];

// ---------------------------------------------------------------------------
// SGEMM: C[M,N] = A[M,K] @ B[K,N], row-major, fp32, f32x2 inner product.
// BM=BN=128, BK=16, 256 threads, 8x8 per-thread tile (pairs along M).
// Requires M%128==0, N%128==0, K%16==0 (true for all 4 GEMMs here).
// ---------------------------------------------------------------------------
#define BM 128
#define BN 128
#define BK 16

__global__ __launch_bounds__(256) void sgemm128(const float* __restrict__ A,
                                                const float* __restrict__ B,
                                                float* __restrict__ C,
                                                int M, int N, int K) {
    __shared__ float As[BK][BM];        // transposed A tile
    __shared__ float Bsd[BK][2 * BN];   // B tile, each value duplicated (for f32x2 bcast)

    const int tid = threadIdx.x;
    const int tx = (tid & 15) * 8;      // col offset within BN
    const int ty = (tid >> 4) * 8;      // row offset within BM

    const float* Ab = A + (size_t)blockIdx.y * BM * K;
    const float* Bb = B + (size_t)blockIdx.x * BN;

    f32x2 acc[4][8];
#pragma unroll
    for (int m = 0; m < 4; m++)
#pragma unroll
        for (int n = 0; n < 8; n++) acc[m][n] = 0ULL;

    for (int k0 = 0; k0 < K; k0 += BK) {
        __syncthreads();
        // ---- load A tile (128x16) transposed ----
#pragma unroll
        for (int i = 0; i < 2; i++) {
            int idx = tid + i * 256;            // 0..511 float4s
            int row = idx >> 2;                 // 0..127
            int kc  = (idx & 3) << 2;           // 0,4,8,12
            float4 v = *(const float4*)(Ab + (size_t)row * K + k0 + kc);
            As[kc + 0][row] = v.x;
            As[kc + 1][row] = v.y;
            As[kc + 2][row] = v.z;
            As[kc + 3][row] = v.w;
        }
        // ---- load B tile (16x128), duplicated per element ----
#pragma unroll
        for (int i = 0; i < 2; i++) {
            int idx = tid + i * 256;
            int row = idx >> 5;                 // 0..15 (k)
            int c4  = idx & 31;                 // col group
            float4 v = *(const float4*)(Bb + (size_t)(k0 + row) * N + c4 * 4);
            float* dst = &Bsd[row][c4 * 8];
            ((float4*)dst)[0] = make_float4(v.x, v.x, v.y, v.y);
            ((float4*)dst)[1] = make_float4(v.z, v.z, v.w, v.w);
        }
        __syncthreads();

#pragma unroll
        for (int k = 0; k < BK; k++) {
            ulonglong2 av0 = *(const ulonglong2*)&As[k][ty];
            ulonglong2 av1 = *(const ulonglong2*)&As[k][ty + 4];
            f32x2 a2[4] = { av0.x, av0.y, av1.x, av1.y };
            const ulonglong2* bp = (const ulonglong2*)&Bsd[k][2 * tx];
            ulonglong2 bv0 = bp[0], bv1 = bp[1], bv2 = bp[2], bv3 = bp[3];
            f32x2 b2[8] = { bv0.x, bv0.y, bv1.x, bv1.y, bv2.x, bv2.y, bv3.x, bv3.y };
#pragma unroll
            for (int m = 0; m < 4; m++)
#pragma unroll
                for (int n = 0; n < 8; n++)
                    acc[m][n] = ffma2(a2[m], b2[n], acc[m][n]);
        }
    }

    // ---- epilogue ----
    float* Cb = C + (size_t)(blockIdx.y * BM) * N + (size_t)blockIdx.x * BN;
#pragma unroll
    for (int m2 = 0; m2 < 4; m2++) {
        float r0[8], r1[8];
#pragma unroll
        for (int n = 0; n < 8; n++) unpack2(acc[m2][n], r0[n], r1[n]);
        float* p0 = Cb + (size_t)(ty + 2 * m2) * N + tx;
        float* p1 = p0 + N;
        ((float4*)p0)[0] = make_float4(r0[0], r0[1], r0[2], r0[3]);
        ((float4*)p0)[1] = make_float4(r0[4], r0[5], r0[6], r0[7]);
        ((float4*)p1)[0] = make_float4(r1[0], r1[1], r1[2], r1[3]);
        ((float4*)p1)[1] = make_float4(r1[4], r1[5], r1[6], r1[7]);
    }
}

// ---------------------------------------------------------------------------
// RMS norm (+optional weight) + 2D RoPE, in place. One warp per (token,head).
// d layout per lane: {lane, lane+32, lane+64 (lane<8)}.
// RoPE (per 36-half): out[d] = y[d]*cos[d] + sgn * y[partner]*sin[d],
//   r=d%36; partner = d - r + (r<18 ? r+18 : r-18); sgn = (r<18 ? -1 : +1).
// ---------------------------------------------------------------------------
__device__ __forceinline__ void norm_one(float* __restrict__ p, const float* w,
                                         const float* __restrict__ cp,
                                         const float* __restrict__ sp,
                                         float* tmp, int lane, bool rope) {
    float x0 = p[lane];
    float x1 = p[lane + 32];
    float x2 = (lane < 8) ? p[lane + 64] : 0.f;
    float ss = x0 * x0 + x1 * x1 + x2 * x2;
#pragma unroll
    for (int off = 16; off; off >>= 1) ss += __shfl_xor_sync(0xffffffffu, ss, off);
    float rs = rsqrtf(ss * (1.0f / 72.0f) + 1e-6f);
    float y0 = x0 * rs, y1 = x1 * rs, y2 = x2 * rs;
    if (w) {
        y0 *= w[lane];
        y1 *= w[lane + 32];
        if (lane < 8) y2 *= w[lane + 64];
    }
    if (!rope) {
        p[lane] = y0;
        p[lane + 32] = y1;
        if (lane < 8) p[lane + 64] = y2;
        return;
    }
    tmp[lane] = y0;
    tmp[lane + 32] = y1;
    if (lane < 8) tmp[lane + 64] = y2;
    __syncwarp();
    float ys[3] = { y0, y1, y2 };
#pragma unroll
    for (int i = 0; i < 3; i++) {
        if (i == 2 && lane >= 8) break;
        int d = lane + 32 * i;
        int r = d % 36;
        int partner = d - r + ((r < QUART) ? r + QUART : r - QUART);
        float sgn = (r < QUART) ? -1.f : 1.f;
        p[d] = ys[i] * cp[d] + sgn * tmp[partner] * sp[d];
    }
    __syncwarp();   // tmp reused by next call
}

__global__ __launch_bounds__(256) void normrope_kernel(
    float* __restrict__ Q, float* __restrict__ Kb, float* __restrict__ V,
    const float* __restrict__ cosg, const float* __restrict__ sing,
    const float* __restrict__ qs, const float* __restrict__ ks) {
    __shared__ float tmp[8][HDIM];
    int warp = threadIdx.x >> 5, lane = threadIdx.x & 31;
    int pair = blockIdx.x * 8 + warp;           // 0 .. 65535
    int tok = pair >> 4, head = pair & 15;
    size_t off = (size_t)tok * HID + head * HDIM;
    const float* cp = cosg + (size_t)tok * HDIM;
    const float* sp = sing + (size_t)tok * HDIM;
    norm_one(Q + off, qs, cp, sp, tmp[warp], lane, true);
    norm_one(Kb + off, ks, cp, sp, tmp[warp], lane, true);
    norm_one(V + off, nullptr, cp, sp, tmp[warp], lane, false);
}

// ---------------------------------------------------------------------------
// Flash attention, fp32, f32x2 inner loops.
// Grid (32, 16): 128 queries per block, one head per blockIdx.y.
// One thread = one query row; K/V streamed through shared in TK=16 tiles.
// ---------------------------------------------------------------------------
#define TK 16

__global__ __launch_bounds__(128) void attn_kernel(const float* __restrict__ Q,
                                                   const float* __restrict__ K,
                                                   const float* __restrict__ V,
                                                   float* __restrict__ O) {
    __shared__ float Ksh[TK][HDIM];
    __shared__ float Vsh[TK][HDIM];

    const int tid = threadIdx.x;
    const int qi = blockIdx.x * 128 + tid;
    const int h = blockIdx.y;

    const float* qp = Q + (size_t)qi * HID + h * HDIM;
    const float* Kh = K + (size_t)h * HDIM;
    const float* Vh = V + (size_t)h * HDIM;

    f32x2 q2[HALF];
#pragma unroll
    for (int i = 0; i < HALF; i++) q2[i] = ((const f32x2*)qp)[i];

    f32x2 o2[HALF];
#pragma unroll
    for (int i = 0; i < HALF; i++) o2[i] = 0ULL;

    float m = -INFINITY, l = 0.f;

    for (int t = 0; t < NTOK / TK; t++) {
        __syncthreads();
        // cooperative K/V tile load: 16x72 each, 9 elems per thread per array
#pragma unroll
        for (int i = 0; i < 9; i++) {
            int idx = tid + i * 128;            // 0..1151
            int r = idx / HDIM;
            int c = idx - r * HDIM;
            size_t g = (size_t)(t * TK + r) * HID + c;
            Ksh[r][c] = Kh[g];
            Vsh[r][c] = Vh[g];
        }
        __syncthreads();

        // ---- scores: s[j] = q . K[j] ----
        f32x2 s2[TK];
#pragma unroll
        for (int j = 0; j < TK; j++) s2[j] = 0ULL;
#pragma unroll
        for (int d2 = 0; d2 < 18; d2++) {
            f32x2 qa = q2[2 * d2];
            f32x2 qb = q2[2 * d2 + 1];
#pragma unroll
            for (int j = 0; j < TK; j++) {
                ulonglong2 kv = *(const ulonglong2*)&Ksh[j][4 * d2];
                s2[j] = ffma2(qa, kv.x, ffma2(qb, kv.y, s2[j]));
            }
        }
        float s[TK];
#pragma unroll
        for (int j = 0; j < TK; j++) {
            float lo, hi;
            unpack2(s2[j], lo, hi);
            s[j] = lo + hi;
        }

        // ---- online softmax update ----
        float tmax = s[0];
#pragma unroll
        for (int j = 1; j < TK; j++) tmax = fmaxf(tmax, s[j]);
        float mn = fmaxf(m, tmax);
        float corr = __expf(m - mn);
        l *= corr;
        f32x2 c2 = pack2(corr, corr);
#pragma unroll
        for (int d = 0; d < HALF; d++) o2[d] = fmul2(o2[d], c2);
        float p[TK];
#pragma unroll
        for (int j = 0; j < TK; j++) {
            p[j] = __expf(s[j] - mn);
            l += p[j];
        }
        m = mn;

        // ---- o += p . V ----
#pragma unroll
        for (int j = 0; j < TK; j++) {
            f32x2 pj = pack2(p[j], p[j]);
#pragma unroll
            for (int d2 = 0; d2 < 18; d2++) {
                ulonglong2 vv = *(const ulonglong2*)&Vsh[j][4 * d2];
                o2[2 * d2]     = ffma2(pj, vv.x, o2[2 * d2]);
                o2[2 * d2 + 1] = ffma2(pj, vv.y, o2[2 * d2 + 1]);
            }
        }
    }

    float inv = 1.0f / l;
    f32x2 iv = pack2(inv, inv);
    float* op = O + (size_t)qi * HID + h * HDIM;
#pragma unroll
    for (int d = 0; d < HALF; d++) ((f32x2*)op)[d] = fmul2(o2[d], iv);
}

// ---------------------------------------------------------------------------
// Launch: QKV gemms -> norm+rope -> flash attention -> out projection
// ---------------------------------------------------------------------------
extern "C" void kernel_launch(void* const* d_in, const int* in_sizes, int n_in,
                              void* d_out, int out_size) {
    const float* X  = (const float*)d_in[0];
    const float* cs = (const float*)d_in[1];
    const float* sn = (const float*)d_in[2];
    const float* Wq = (const float*)d_in[3];
    const float* Wk = (const float*)d_in[4];
    const float* Wv = (const float*)d_in[5];
    const float* Wo = (const float*)d_in[6];
    const float* qs = (const float*)d_in[7];
    const float* ks = (const float*)d_in[8];
    float* out = (float*)d_out;

    static float *bq = nullptr, *bk = nullptr, *bv = nullptr, *bo = nullptr;
    if (!bq) {
        cudaGetSymbolAddress((void**)&bq, g_bufQ);
        cudaGetSymbolAddress((void**)&bk, g_bufK);
        cudaGetSymbolAddress((void**)&bv, g_bufV);
        cudaGetSymbolAddress((void**)&bo, g_bufO);
    }

    dim3 gg(HID / BN, NTOK / BM);   // (9, 32)
    sgemm128<<<gg, 256>>>(X, Wq, bq, NTOK, HID, HID);
    sgemm128<<<gg, 256>>>(X, Wk, bk, NTOK, HID, HID);
    sgemm128<<<gg, 256>>>(X, Wv, bv, NTOK, HID, HID);

    normrope_kernel<<<(NTOK * NHEAD) / 8, 256>>>(bq, bk, bv, cs, sn, qs, ks);

    attn_kernel<<<dim3(NTOK / 128, NHEAD), 128>>>(bq, bk, bv, bo);

    sgemm128<<<gg, 256>>>(bo, Wo, out, NTOK, HID, HID);
}

// round 2
// speedup vs baseline: 1.2680x; 1.2680x over previous
#include <cuda_runtime.h>
#include <cstdint>

// ---------------------------------------------------------------------------
// Problem constants
// ---------------------------------------------------------------------------
#define NTOK   4096
#define HID    1152
#define NHEAD  16
#define HDIM   72
#define HALF   36
#define QUART  18

// ---------------------------------------------------------------------------
// Packed f32x2 helpers (sm_103a FFMA2 path — 2x fp32 throughput vs FFMA)
// ---------------------------------------------------------------------------
typedef unsigned long long f32x2;

__device__ __forceinline__ f32x2 ffma2(f32x2 a, f32x2 b, f32x2 c) {
    f32x2 d;
    asm("fma.rn.f32x2 %0, %1, %2, %3;" : "=l"(d) : "l"(a), "l"(b), "l"(c));
    return d;
}
__device__ __forceinline__ f32x2 fmul2(f32x2 a, f32x2 b) {
    f32x2 d;
    asm("mul.rn.f32x2 %0, %1, %2;" : "=l"(d) : "l"(a), "l"(b));
    return d;
}
__device__ __forceinline__ f32x2 pack2(float lo, float hi) {
    f32x2 d;
    asm("mov.b64 %0, {%1, %2};" : "=l"(d) : "f"(lo), "f"(hi));
    return d;
}
__device__ __forceinline__ void unpack2(f32x2 v, float& lo, float& hi) {
    asm("mov.b64 {%0, %1}, %2;" : "=f"(lo), "=f"(hi) : "l"(v));
}

// ---------------------------------------------------------------------------
// Scratch buffers (no cudaMalloc allowed)
// ---------------------------------------------------------------------------
__device__ float g_bufQ[NTOK * HID];
__device__ float g_bufK[NTOK * HID];
__device__ float g_bufV[NTOK * HID];
__device__ float g_bufO[NTOK * HID];

// ---------------------------------------------------------------------------
// SGEMM v2: C[M,N] = A[M,K] @ B[K,N], fp32, FFMA2-pipe-bound design.
// BM=256, BN=128, BK=16, 256 threads, 16(m) x 8(n) per-thread tile.
// m-pair f32x2 packing: a-pairs natural from transposed A tile, B duplicated
// at smem-store time. Register prefetch double buffering.
// Grid (N/128, M/256) = (9, 16) = 144 blocks -> one wave on 148 SMs.
// ---------------------------------------------------------------------------
#define BM 256
#define BN 128
#define BK 16
#define ASTR (BM + 4)   // 260: 16B-aligned rows, 2-way-max store conflicts

__global__ __launch_bounds__(256) void sgemm256(const float* __restrict__ A,
                                                const float* __restrict__ B,
                                                float* __restrict__ C,
                                                int M, int N, int K) {
    __shared__ float As[BK * ASTR];       // As[k][m] transposed
    __shared__ float Bs2[BK][2 * BN];     // B duplicated per element

    const int tid = threadIdx.x;
    const int tx = (tid & 15) * 8;        // n offset
    const int ty = (tid >> 4) * 16;       // m offset

    const float* Ab = A + (size_t)blockIdx.y * BM * K;
    const float* Bb = B + (size_t)blockIdx.x * BN;

    f32x2 acc[8][8];
#pragma unroll
    for (int m = 0; m < 8; m++)
#pragma unroll
        for (int n = 0; n < 8; n++) acc[m][n] = 0ULL;

    // ---- preload tile 0 into registers ----
    float4 ra[4], rb[2];
#pragma unroll
    for (int i = 0; i < 4; i++) {
        int idx = tid + i * 256;
        int r = idx >> 2, kc = (idx & 3) << 2;
        ra[i] = *(const float4*)(Ab + (size_t)r * K + kc);
    }
#pragma unroll
    for (int i = 0; i < 2; i++) {
        int idx = tid + i * 256;
        int r = idx >> 5, c4 = idx & 31;
        rb[i] = *(const float4*)(Bb + (size_t)r * N + c4 * 4);
    }

    for (int k0 = 0; k0 < K; k0 += BK) {
        __syncthreads();
        // ---- store prefetched tile to smem ----
#pragma unroll
        for (int i = 0; i < 4; i++) {
            int idx = tid + i * 256;
            int r = idx >> 2, kc = (idx & 3) << 2;
            As[(kc + 0) * ASTR + r] = ra[i].x;
            As[(kc + 1) * ASTR + r] = ra[i].y;
            As[(kc + 2) * ASTR + r] = ra[i].z;
            As[(kc + 3) * ASTR + r] = ra[i].w;
        }
#pragma unroll
        for (int i = 0; i < 2; i++) {
            int idx = tid + i * 256;
            int r = idx >> 5, c4 = idx & 31;
            float* dst = &Bs2[r][c4 * 8];
            ((float4*)dst)[0] = make_float4(rb[i].x, rb[i].x, rb[i].y, rb[i].y);
            ((float4*)dst)[1] = make_float4(rb[i].z, rb[i].z, rb[i].w, rb[i].w);
        }
        __syncthreads();

        // ---- prefetch next tile (overlaps with compute below) ----
        if (k0 + BK < K) {
            const float* An = Ab + k0 + BK;
            const float* Bn = Bb + (size_t)(k0 + BK) * N;
#pragma unroll
            for (int i = 0; i < 4; i++) {
                int idx = tid + i * 256;
                int r = idx >> 2, kc = (idx & 3) << 2;
                ra[i] = *(const float4*)(An + (size_t)r * K + kc);
            }
#pragma unroll
            for (int i = 0; i < 2; i++) {
                int idx = tid + i * 256;
                int r = idx >> 5, c4 = idx & 31;
                rb[i] = *(const float4*)(Bn + (size_t)r * N + c4 * 4);
            }
        }

        // ---- compute ----
#pragma unroll
        for (int k = 0; k < BK; k++) {
            const ulonglong2* ap = (const ulonglong2*)&As[k * ASTR + ty];
            ulonglong2 av0 = ap[0], av1 = ap[1], av2 = ap[2], av3 = ap[3];
            f32x2 a2[8] = { av0.x, av0.y, av1.x, av1.y, av2.x, av2.y, av3.x, av3.y };
            const ulonglong2* bp = (const ulonglong2*)&Bs2[k][2 * tx];
            ulonglong2 bv0 = bp[0], bv1 = bp[1], bv2 = bp[2], bv3 = bp[3];
            f32x2 b2[8] = { bv0.x, bv0.y, bv1.x, bv1.y, bv2.x, bv2.y, bv3.x, bv3.y };
#pragma unroll
            for (int m = 0; m < 8; m++)
#pragma unroll
                for (int n = 0; n < 8; n++)
                    acc[m][n] = ffma2(a2[m], b2[n], acc[m][n]);
        }
    }

    // ---- epilogue: acc[m2][n] = (C[ty+2m2][tx+n], C[ty+2m2+1][tx+n]) ----
    float* Cb = C + (size_t)(blockIdx.y * BM) * N + (size_t)blockIdx.x * BN;
#pragma unroll
    for (int m2 = 0; m2 < 8; m2++) {
        float r0[8], r1[8];
#pragma unroll
        for (int n = 0; n < 8; n++) unpack2(acc[m2][n], r0[n], r1[n]);
        float* p0 = Cb + (size_t)(ty + 2 * m2) * N + tx;
        float* p1 = p0 + N;
        ((float4*)p0)[0] = make_float4(r0[0], r0[1], r0[2], r0[3]);
        ((float4*)p0)[1] = make_float4(r0[4], r0[5], r0[6], r0[7]);
        ((float4*)p1)[0] = make_float4(r1[0], r1[1], r1[2], r1[3]);
        ((float4*)p1)[1] = make_float4(r1[4], r1[5], r1[6], r1[7]);
    }
}

// ---------------------------------------------------------------------------
// RMS norm (+optional weight) + 2D RoPE, in place. One warp per (token,head).
// ---------------------------------------------------------------------------
__device__ __forceinline__ void norm_one(float* __restrict__ p, const float* w,
                                         const float* __restrict__ cp,
                                         const float* __restrict__ sp,
                                         float* tmp, int lane, bool rope) {
    float x0 = p[lane];
    float x1 = p[lane + 32];
    float x2 = (lane < 8) ? p[lane + 64] : 0.f;
    float ss = x0 * x0 + x1 * x1 + x2 * x2;
#pragma unroll
    for (int off = 16; off; off >>= 1) ss += __shfl_xor_sync(0xffffffffu, ss, off);
    float rs = rsqrtf(ss * (1.0f / 72.0f) + 1e-6f);
    float y0 = x0 * rs, y1 = x1 * rs, y2 = x2 * rs;
    if (w) {
        y0 *= w[lane];
        y1 *= w[lane + 32];
        if (lane < 8) y2 *= w[lane + 64];
    }
    if (!rope) {
        p[lane] = y0;
        p[lane + 32] = y1;
        if (lane < 8) p[lane + 64] = y2;
        return;
    }
    tmp[lane] = y0;
    tmp[lane + 32] = y1;
    if (lane < 8) tmp[lane + 64] = y2;
    __syncwarp();
    float ys[3] = { y0, y1, y2 };
#pragma unroll
    for (int i = 0; i < 3; i++) {
        if (i == 2 && lane >= 8) break;
        int d = lane + 32 * i;
        int r = d % 36;
        int partner = d - r + ((r < QUART) ? r + QUART : r - QUART);
        float sgn = (r < QUART) ? -1.f : 1.f;
        p[d] = ys[i] * cp[d] + sgn * tmp[partner] * sp[d];
    }
    __syncwarp();
}

__global__ __launch_bounds__(256) void normrope_kernel(
    float* __restrict__ Q, float* __restrict__ Kb, float* __restrict__ V,
    const float* __restrict__ cosg, const float* __restrict__ sing,
    const float* __restrict__ qs, const float* __restrict__ ks) {
    __shared__ float tmp[8][HDIM];
    int warp = threadIdx.x >> 5, lane = threadIdx.x & 31;
    int pair = blockIdx.x * 8 + warp;
    int tok = pair >> 4, head = pair & 15;
    size_t off = (size_t)tok * HID + head * HDIM;
    const float* cp = cosg + (size_t)tok * HDIM;
    const float* sp = sing + (size_t)tok * HDIM;
    norm_one(Q + off, qs, cp, sp, tmp[warp], lane, true);
    norm_one(Kb + off, ks, cp, sp, tmp[warp], lane, true);
    norm_one(V + off, nullptr, cp, sp, tmp[warp], lane, false);
}

// ---------------------------------------------------------------------------
// Flash attention, fp32, f32x2 inner loops.
// Grid (32, 16): 128 queries/block, one head per blockIdx.y, 1 query/thread.
// Hoisted tile-load addressing; lean register budget (no spills).
// ---------------------------------------------------------------------------
#define TK 16

__global__ __launch_bounds__(128) void attn_kernel(const float* __restrict__ Q,
                                                   const float* __restrict__ K,
                                                   const float* __restrict__ V,
                                                   float* __restrict__ O) {
    __shared__ float Ksh[TK][HDIM];
    __shared__ float Vsh[TK][HDIM];

    const int tid = threadIdx.x;
    const int qi = blockIdx.x * 128 + tid;
    const int h = blockIdx.y;

    const float* qp = Q + (size_t)qi * HID + h * HDIM;
    const float* Kh = K + (size_t)h * HDIM;
    const float* Vh = V + (size_t)h * HDIM;

    // hoisted cooperative-load coordinates (t-invariant)
    int ldoff[9], ldsmem[9];
#pragma unroll
    for (int i = 0; i < 9; i++) {
        int idx = tid + i * 128;            // 0..1151
        int r = idx / HDIM;
        int c = idx - r * HDIM;
        ldoff[i] = r * HID + c;             // global offset within tile
        ldsmem[i] = r * HDIM + c;           // smem offset
    }

    f32x2 q2[HALF];
#pragma unroll
    for (int i = 0; i < HALF; i++) q2[i] = ((const f32x2*)qp)[i];

    f32x2 o2[HALF];
#pragma unroll
    for (int i = 0; i < HALF; i++) o2[i] = 0ULL;

    float m = -INFINITY, l = 0.f;

    for (int t = 0; t < NTOK / TK; t++) {
        const size_t gbase = (size_t)t * TK * HID;
        __syncthreads();
#pragma unroll
        for (int i = 0; i < 9; i++) {
            ((float*)Ksh)[ldsmem[i]] = Kh[gbase + ldoff[i]];
            ((float*)Vsh)[ldsmem[i]] = Vh[gbase + ldoff[i]];
        }
        __syncthreads();

        // ---- scores ----
        f32x2 s2[TK];
#pragma unroll
        for (int j = 0; j < TK; j++) s2[j] = 0ULL;
#pragma unroll
        for (int d2 = 0; d2 < 18; d2++) {
            f32x2 qa = q2[2 * d2];
            f32x2 qb = q2[2 * d2 + 1];
#pragma unroll
            for (int j = 0; j < TK; j++) {
                ulonglong2 kv = *(const ulonglong2*)&Ksh[j][4 * d2];
                s2[j] = ffma2(qa, kv.x, ffma2(qb, kv.y, s2[j]));
            }
        }
        float s[TK];
#pragma unroll
        for (int j = 0; j < TK; j++) {
            float lo, hi;
            unpack2(s2[j], lo, hi);
            s[j] = lo + hi;
        }

        // ---- online softmax ----
        float tmax = s[0];
#pragma unroll
        for (int j = 1; j < TK; j++) tmax = fmaxf(tmax, s[j]);
        float mn = fmaxf(m, tmax);
        float corr = __expf(m - mn);
        l *= corr;
        f32x2 c2 = pack2(corr, corr);
#pragma unroll
        for (int d = 0; d < HALF; d++) o2[d] = fmul2(o2[d], c2);
        float p[TK];
#pragma unroll
        for (int j = 0; j < TK; j++) {
            p[j] = __expf(s[j] - mn);
            l += p[j];
        }
        m = mn;

        // ---- o += p . V ----
#pragma unroll
        for (int j = 0; j < TK; j++) {
            f32x2 pj = pack2(p[j], p[j]);
#pragma unroll
            for (int d2 = 0; d2 < 18; d2++) {
                ulonglong2 vv = *(const ulonglong2*)&Vsh[j][4 * d2];
                o2[2 * d2]     = ffma2(pj, vv.x, o2[2 * d2]);
                o2[2 * d2 + 1] = ffma2(pj, vv.y, o2[2 * d2 + 1]);
            }
        }
    }

    float inv = 1.0f / l;
    f32x2 iv = pack2(inv, inv);
    float* op = O + (size_t)qi * HID + h * HDIM;
#pragma unroll
    for (int d = 0; d < HALF; d++) ((f32x2*)op)[d] = fmul2(o2[d], iv);
}

// ---------------------------------------------------------------------------
// Launch
// ---------------------------------------------------------------------------
extern "C" void kernel_launch(void* const* d_in, const int* in_sizes, int n_in,
                              void* d_out, int out_size) {
    const float* X  = (const float*)d_in[0];
    const float* cs = (const float*)d_in[1];
    const float* sn = (const float*)d_in[2];
    const float* Wq = (const float*)d_in[3];
    const float* Wk = (const float*)d_in[4];
    const float* Wv = (const float*)d_in[5];
    const float* Wo = (const float*)d_in[6];
    const float* qs = (const float*)d_in[7];
    const float* ks = (const float*)d_in[8];
    float* out = (float*)d_out;

    static float *bq = nullptr, *bk = nullptr, *bv = nullptr, *bo = nullptr;
    if (!bq) {
        cudaGetSymbolAddress((void**)&bq, g_bufQ);
        cudaGetSymbolAddress((void**)&bk, g_bufK);
        cudaGetSymbolAddress((void**)&bv, g_bufV);
        cudaGetSymbolAddress((void**)&bo, g_bufO);
    }

    dim3 gg(HID / BN, NTOK / BM);   // (9, 16) = 144 blocks
    sgemm256<<<gg, 256>>>(X, Wq, bq, NTOK, HID, HID);
    sgemm256<<<gg, 256>>>(X, Wk, bk, NTOK, HID, HID);
    sgemm256<<<gg, 256>>>(X, Wv, bv, NTOK, HID, HID);

    normrope_kernel<<<(NTOK * NHEAD) / 8, 256>>>(bq, bk, bv, cs, sn, qs, ks);

    attn_kernel<<<dim3(NTOK / 128, NHEAD), 128>>>(bq, bk, bv, bo);

    sgemm256<<<gg, 256>>>(bo, Wo, out, NTOK, HID, HID);
}

// round 4
// speedup vs baseline: 2.2606x; 1.7828x over previous
#include <cuda_runtime.h>
#include <cuda_fp16.h>
#include <cstdint>

// ---------------------------------------------------------------------------
// Problem constants
// ---------------------------------------------------------------------------
#define NTOK   4096
#define HID    1152
#define NHEAD  16
#define HDIM   72
#define QUART  18
#define LOG2E  1.4426950408889634f

typedef unsigned long long f32x2;

__device__ __forceinline__ f32x2 ffma2(f32x2 a, f32x2 b, f32x2 c) {
    f32x2 d; asm("fma.rn.f32x2 %0, %1, %2, %3;" : "=l"(d) : "l"(a), "l"(b), "l"(c)); return d;
}
__device__ __forceinline__ void unpack2(f32x2 v, float& lo, float& hi) {
    asm("mov.b64 {%0, %1}, %2;" : "=f"(lo), "=f"(hi) : "l"(v));
}
__device__ __forceinline__ float ex2f(float x) {
    float y; asm("ex2.approx.f32 %0, %1;" : "=f"(y) : "f"(x)); return y;
}
__device__ __forceinline__ uint32_t cvt_tf32(float x) {
    uint32_t r; asm("cvt.rna.tf32.f32 %0, %1;" : "=r"(r) : "f"(x)); return r;
}

// mma.sync m16n8k8 tf32 (fp32 accum)
__device__ __forceinline__ void mma_tf32(float* d, const uint32_t* a, const uint32_t* b,
                                         const float* c) {
    asm volatile(
        "mma.sync.aligned.m16n8k8.row.col.f32.tf32.tf32.f32 "
        "{%0,%1,%2,%3}, {%4,%5,%6,%7}, {%8,%9}, {%10,%11,%12,%13};"
        : "=f"(d[0]), "=f"(d[1]), "=f"(d[2]), "=f"(d[3])
        : "r"(a[0]), "r"(a[1]), "r"(a[2]), "r"(a[3]), "r"(b[0]), "r"(b[1]),
          "f"(c[0]), "f"(c[1]), "f"(c[2]), "f"(c[3]));
}

// mma.sync m16n8k16 fp16 (fp32 accum)
__device__ __forceinline__ void mma_f16(float* d, const uint32_t* a, const uint32_t* b,
                                        const float* c) {
    asm volatile(
        "mma.sync.aligned.m16n8k16.row.col.f32.f16.f16.f32 "
        "{%0,%1,%2,%3}, {%4,%5,%6,%7}, {%8,%9}, {%10,%11,%12,%13};"
        : "=f"(d[0]), "=f"(d[1]), "=f"(d[2]), "=f"(d[3])
        : "r"(a[0]), "r"(a[1]), "r"(a[2]), "r"(a[3]), "r"(b[0]), "r"(b[1]),
          "f"(c[0]), "f"(c[1]), "f"(c[2]), "f"(c[3]));
}

// ---------------------------------------------------------------------------
// Scratch buffers
// ---------------------------------------------------------------------------
__device__ float g_bufQ[NTOK * HID];
__device__ float g_bufK[NTOK * HID];
__device__ float g_bufV[NTOK * HID];
__device__ float g_bufO[NTOK * HID];

// ---------------------------------------------------------------------------
// SGEMM (unchanged from R2): BM=256 BN=128 BK=16, f32x2, prefetch
// ---------------------------------------------------------------------------
#define BM 256
#define BN 128
#define BK 16
#define ASTR (BM + 4)

__global__ __launch_bounds__(256) void sgemm256(const float* __restrict__ A,
                                                const float* __restrict__ B,
                                                float* __restrict__ C,
                                                int M, int N, int K) {
    __shared__ float As[BK * ASTR];
    __shared__ float Bs2[BK][2 * BN];
    const int tid = threadIdx.x;
    const int tx = (tid & 15) * 8;
    const int ty = (tid >> 4) * 16;
    const float* Ab = A + (size_t)blockIdx.y * BM * K;
    const float* Bb = B + (size_t)blockIdx.x * BN;

    f32x2 acc[8][8];
#pragma unroll
    for (int m = 0; m < 8; m++)
#pragma unroll
        for (int n = 0; n < 8; n++) acc[m][n] = 0ULL;

    float4 ra[4], rb[2];
#pragma unroll
    for (int i = 0; i < 4; i++) {
        int idx = tid + i * 256; int r = idx >> 2, kc = (idx & 3) << 2;
        ra[i] = *(const float4*)(Ab + (size_t)r * K + kc);
    }
#pragma unroll
    for (int i = 0; i < 2; i++) {
        int idx = tid + i * 256; int r = idx >> 5, c4 = idx & 31;
        rb[i] = *(const float4*)(Bb + (size_t)r * N + c4 * 4);
    }

    for (int k0 = 0; k0 < K; k0 += BK) {
        __syncthreads();
#pragma unroll
        for (int i = 0; i < 4; i++) {
            int idx = tid + i * 256; int r = idx >> 2, kc = (idx & 3) << 2;
            As[(kc + 0) * ASTR + r] = ra[i].x;
            As[(kc + 1) * ASTR + r] = ra[i].y;
            As[(kc + 2) * ASTR + r] = ra[i].z;
            As[(kc + 3) * ASTR + r] = ra[i].w;
        }
#pragma unroll
        for (int i = 0; i < 2; i++) {
            int idx = tid + i * 256; int r = idx >> 5, c4 = idx & 31;
            float* dst = &Bs2[r][c4 * 8];
            ((float4*)dst)[0] = make_float4(rb[i].x, rb[i].x, rb[i].y, rb[i].y);
            ((float4*)dst)[1] = make_float4(rb[i].z, rb[i].z, rb[i].w, rb[i].w);
        }
        __syncthreads();
        if (k0 + BK < K) {
            const float* An = Ab + k0 + BK;
            const float* Bn = Bb + (size_t)(k0 + BK) * N;
#pragma unroll
            for (int i = 0; i < 4; i++) {
                int idx = tid + i * 256; int r = idx >> 2, kc = (idx & 3) << 2;
                ra[i] = *(const float4*)(An + (size_t)r * K + kc);
            }
#pragma unroll
            for (int i = 0; i < 2; i++) {
                int idx = tid + i * 256; int r = idx >> 5, c4 = idx & 31;
                rb[i] = *(const float4*)(Bn + (size_t)r * N + c4 * 4);
            }
        }
#pragma unroll
        for (int k = 0; k < BK; k++) {
            const ulonglong2* ap = (const ulonglong2*)&As[k * ASTR + ty];
            ulonglong2 av0 = ap[0], av1 = ap[1], av2 = ap[2], av3 = ap[3];
            f32x2 a2[8] = { av0.x, av0.y, av1.x, av1.y, av2.x, av2.y, av3.x, av3.y };
            const ulonglong2* bp = (const ulonglong2*)&Bs2[k][2 * tx];
            ulonglong2 bv0 = bp[0], bv1 = bp[1], bv2 = bp[2], bv3 = bp[3];
            f32x2 b2[8] = { bv0.x, bv0.y, bv1.x, bv1.y, bv2.x, bv2.y, bv3.x, bv3.y };
#pragma unroll
            for (int m = 0; m < 8; m++)
#pragma unroll
                for (int n = 0; n < 8; n++)
                    acc[m][n] = ffma2(a2[m], b2[n], acc[m][n]);
        }
    }
    float* Cb = C + (size_t)(blockIdx.y * BM) * N + (size_t)blockIdx.x * BN;
#pragma unroll
    for (int m2 = 0; m2 < 8; m2++) {
        float r0[8], r1[8];
#pragma unroll
        for (int n = 0; n < 8; n++) unpack2(acc[m2][n], r0[n], r1[n]);
        float* p0 = Cb + (size_t)(ty + 2 * m2) * N + tx;
        float* p1 = p0 + N;
        ((float4*)p0)[0] = make_float4(r0[0], r0[1], r0[2], r0[3]);
        ((float4*)p0)[1] = make_float4(r0[4], r0[5], r0[6], r0[7]);
        ((float4*)p1)[0] = make_float4(r1[0], r1[1], r1[2], r1[3]);
        ((float4*)p1)[1] = make_float4(r1[4], r1[5], r1[6], r1[7]);
    }
}

// ---------------------------------------------------------------------------
// RMS norm + RoPE (unchanged)
// ---------------------------------------------------------------------------
__device__ __forceinline__ void norm_one(float* __restrict__ p, const float* w,
                                         const float* __restrict__ cp,
                                         const float* __restrict__ sp,
                                         float* tmp, int lane, bool rope) {
    float x0 = p[lane];
    float x1 = p[lane + 32];
    float x2 = (lane < 8) ? p[lane + 64] : 0.f;
    float ss = x0 * x0 + x1 * x1 + x2 * x2;
#pragma unroll
    for (int off = 16; off; off >>= 1) ss += __shfl_xor_sync(0xffffffffu, ss, off);
    float rs = rsqrtf(ss * (1.0f / 72.0f) + 1e-6f);
    float y0 = x0 * rs, y1 = x1 * rs, y2 = x2 * rs;
    if (w) { y0 *= w[lane]; y1 *= w[lane + 32]; if (lane < 8) y2 *= w[lane + 64]; }
    if (!rope) {
        p[lane] = y0; p[lane + 32] = y1; if (lane < 8) p[lane + 64] = y2;
        return;
    }
    tmp[lane] = y0; tmp[lane + 32] = y1;
    if (lane < 8) tmp[lane + 64] = y2;
    __syncwarp();
    float ys[3] = { y0, y1, y2 };
#pragma unroll
    for (int i = 0; i < 3; i++) {
        if (i == 2 && lane >= 8) break;
        int d = lane + 32 * i;
        int r = d % 36;
        int partner = d - r + ((r < QUART) ? r + QUART : r - QUART);
        float sgn = (r < QUART) ? -1.f : 1.f;
        p[d] = ys[i] * cp[d] + sgn * tmp[partner] * sp[d];
    }
    __syncwarp();
}

__global__ __launch_bounds__(256) void normrope_kernel(
    float* __restrict__ Q, float* __restrict__ Kb, float* __restrict__ V,
    const float* __restrict__ cosg, const float* __restrict__ sing,
    const float* __restrict__ qs, const float* __restrict__ ks) {
    __shared__ float tmp[8][HDIM];
    int warp = threadIdx.x >> 5, lane = threadIdx.x & 31;
    int pair = blockIdx.x * 8 + warp;
    int tok = pair >> 4, head = pair & 15;
    size_t off = (size_t)tok * HID + head * HDIM;
    const float* cp = cosg + (size_t)tok * HDIM;
    const float* sp = sing + (size_t)tok * HDIM;
    norm_one(Q + off, qs, cp, sp, tmp[warp], lane, true);
    norm_one(Kb + off, ks, cp, sp, tmp[warp], lane, true);
    norm_one(V + off, nullptr, cp, sp, tmp[warp], lane, false);
}

// ---------------------------------------------------------------------------
// mma.sync flash attention (tf32 QK^T, fp16 PV, fp32 accum).
// Block: 256 threads = 8 warps, 128 queries (16 rows/warp), one head.
// 64-key tiles through SMEM. grid = (4096/128, 16) = (32, 16).
// ---------------------------------------------------------------------------
#define TKEY 64
#define KSTR 76     // Ks word stride: 76 % 32 = 12 -> conflict-free B-frag LDS
#define VSTR 72     // VTs half stride: 36 words % 32 = 4 -> conflict-free

__global__ __launch_bounds__(256, 1) void attn_mma(const float* __restrict__ Q,
                                                   const float* __restrict__ K,
                                                   const float* __restrict__ V,
                                                   float* __restrict__ O) {
    __shared__ uint32_t Ks[TKEY][KSTR];   // tf32 bits, [key][d]
    __shared__ __half   VTs[HDIM][VSTR];  // fp16, [d][key]

    const int tid = threadIdx.x;
    const int warp = tid >> 5, lane = tid & 31;
    const int g = lane >> 2, t = lane & 3;
    const int h = blockIdx.y;
    const int qbase = blockIdx.x * 128 + warp * 16;

    // ---- Q fragments (scaled by log2e, tf32) ----
    uint32_t qf[9][4];
    {
        const float* q0 = Q + (size_t)(qbase + g) * HID + h * HDIM;
        const float* q1 = q0 + 8 * HID;
#pragma unroll
        for (int c = 0; c < 9; c++) {
            qf[c][0] = cvt_tf32(q0[8 * c + t] * LOG2E);
            qf[c][1] = cvt_tf32(q1[8 * c + t] * LOG2E);
            qf[c][2] = cvt_tf32(q0[8 * c + t + 4] * LOG2E);
            qf[c][3] = cvt_tf32(q1[8 * c + t + 4] * LOG2E);
        }
    }

    float of[9][4];
#pragma unroll
    for (int n = 0; n < 9; n++)
#pragma unroll
        for (int j = 0; j < 4; j++) of[n][j] = 0.f;
    float m0 = -INFINITY, m1 = -INFINITY, l0 = 0.f, l1 = 0.f;

    for (int tt = 0; tt < NTOK / TKEY; tt++) {
        __syncthreads();
        // ---- cooperative K/V tile load (64 x 72) ----
        {
            const float* kg = K + (size_t)(tt * TKEY) * HID + h * HDIM;
            const float* vg = V + (size_t)(tt * TKEY) * HID + h * HDIM;
#pragma unroll
            for (int idx = tid; idx < TKEY * 18; idx += 256) {
                int row = idx / 18, c4 = idx % 18;
                float4 kv = *(const float4*)(kg + (size_t)row * HID + c4 * 4);
                Ks[row][c4 * 4 + 0] = cvt_tf32(kv.x);
                Ks[row][c4 * 4 + 1] = cvt_tf32(kv.y);
                Ks[row][c4 * 4 + 2] = cvt_tf32(kv.z);
                Ks[row][c4 * 4 + 3] = cvt_tf32(kv.w);
                float4 vv = *(const float4*)(vg + (size_t)row * HID + c4 * 4);
                VTs[c4 * 4 + 0][row] = __float2half(vv.x);
                VTs[c4 * 4 + 1][row] = __float2half(vv.y);
                VTs[c4 * 4 + 2][row] = __float2half(vv.z);
                VTs[c4 * 4 + 3][row] = __float2half(vv.w);
            }
        }
        __syncthreads();

        // ---- S = Q K^T : 8 n-tiles (8 keys) x 9 k-chunks ----
        float s[8][4];
#pragma unroll
        for (int n = 0; n < 8; n++) {
            s[n][0] = s[n][1] = s[n][2] = s[n][3] = 0.f;
            const int key = n * 8 + g;
#pragma unroll
            for (int c = 0; c < 9; c++) {
                uint32_t b[2];
                b[0] = Ks[key][8 * c + t];
                b[1] = Ks[key][8 * c + t + 4];
                mma_tf32(s[n], qf[c], b, s[n]);
            }
        }

        // ---- online softmax (quad-local) ----
        float rm0 = -INFINITY, rm1 = -INFINITY;
#pragma unroll
        for (int n = 0; n < 8; n++) {
            rm0 = fmaxf(rm0, fmaxf(s[n][0], s[n][1]));
            rm1 = fmaxf(rm1, fmaxf(s[n][2], s[n][3]));
        }
        rm0 = fmaxf(rm0, __shfl_xor_sync(0xffffffffu, rm0, 1));
        rm0 = fmaxf(rm0, __shfl_xor_sync(0xffffffffu, rm0, 2));
        rm1 = fmaxf(rm1, __shfl_xor_sync(0xffffffffu, rm1, 1));
        rm1 = fmaxf(rm1, __shfl_xor_sync(0xffffffffu, rm1, 2));
        float nm0 = fmaxf(m0, rm0), nm1 = fmaxf(m1, rm1);
        float corr0 = ex2f(m0 - nm0), corr1 = ex2f(m1 - nm1);
        m0 = nm0; m1 = nm1;

        float rs0 = 0.f, rs1 = 0.f;
        uint32_t ph0[8], ph1[8];
#pragma unroll
        for (int n = 0; n < 8; n++) {
            float p0 = ex2f(s[n][0] - m0);
            float p1 = ex2f(s[n][1] - m0);
            float p2 = ex2f(s[n][2] - m1);
            float p3 = ex2f(s[n][3] - m1);
            rs0 += p0 + p1;
            rs1 += p2 + p3;
            __half2 h0 = __floats2half2_rn(p0, p1);
            __half2 h1 = __floats2half2_rn(p2, p3);
            ph0[n] = *(uint32_t*)&h0;
            ph1[n] = *(uint32_t*)&h1;
        }
        rs0 += __shfl_xor_sync(0xffffffffu, rs0, 1);
        rs0 += __shfl_xor_sync(0xffffffffu, rs0, 2);
        rs1 += __shfl_xor_sync(0xffffffffu, rs1, 1);
        rs1 += __shfl_xor_sync(0xffffffffu, rs1, 2);
        l0 = l0 * corr0 + rs0;
        l1 = l1 * corr1 + rs1;

#pragma unroll
        for (int n = 0; n < 9; n++) {
            of[n][0] *= corr0; of[n][1] *= corr0;
            of[n][2] *= corr1; of[n][3] *= corr1;
        }

        // ---- O += P V : 4 key-chunks (16) x 9 d-tiles (8) ----
#pragma unroll
        for (int kc = 0; kc < 4; kc++) {
            uint32_t a[4] = { ph0[2 * kc], ph1[2 * kc], ph0[2 * kc + 1], ph1[2 * kc + 1] };
#pragma unroll
            for (int nt = 0; nt < 9; nt++) {
                const int d = 8 * nt + g;
                const int key = 16 * kc + 2 * t;
                uint32_t b[2];
                b[0] = *(const uint32_t*)&VTs[d][key];
                b[1] = *(const uint32_t*)&VTs[d][key + 8];
                mma_f16(of[nt], a, b, of[nt]);
            }
        }
    }

    // ---- epilogue ----
    {
        float inv0 = 1.0f / l0, inv1 = 1.0f / l1;
        float* o0 = O + (size_t)(qbase + g) * HID + h * HDIM;
        float* o1 = o0 + 8 * HID;
#pragma unroll
        for (int nt = 0; nt < 9; nt++) {
            int col = 8 * nt + 2 * t;
            *(float2*)(o0 + col) = make_float2(of[nt][0] * inv0, of[nt][1] * inv0);
            *(float2*)(o1 + col) = make_float2(of[nt][2] * inv1, of[nt][3] * inv1);
        }
    }
}

// ---------------------------------------------------------------------------
// Launch
// ---------------------------------------------------------------------------
extern "C" void kernel_launch(void* const* d_in, const int* in_sizes, int n_in,
                              void* d_out, int out_size) {
    const float* X  = (const float*)d_in[0];
    const float* cs = (const float*)d_in[1];
    const float* sn = (const float*)d_in[2];
    const float* Wq = (const float*)d_in[3];
    const float* Wk = (const float*)d_in[4];
    const float* Wv = (const float*)d_in[5];
    const float* Wo = (const float*)d_in[6];
    const float* qs = (const float*)d_in[7];
    const float* ks = (const float*)d_in[8];
    float* out = (float*)d_out;

    static float *bq = nullptr, *bk = nullptr, *bv = nullptr, *bo = nullptr;
    if (!bq) {
        cudaGetSymbolAddress((void**)&bq, g_bufQ);
        cudaGetSymbolAddress((void**)&bk, g_bufK);
        cudaGetSymbolAddress((void**)&bv, g_bufV);
        cudaGetSymbolAddress((void**)&bo, g_bufO);
    }

    dim3 gg(HID / BN, NTOK / BM);   // (9, 16)
    sgemm256<<<gg, 256>>>(X, Wq, bq, NTOK, HID, HID);
    sgemm256<<<gg, 256>>>(X, Wk, bk, NTOK, HID, HID);
    sgemm256<<<gg, 256>>>(X, Wv, bv, NTOK, HID, HID);

    normrope_kernel<<<(NTOK * NHEAD) / 8, 256>>>(bq, bk, bv, cs, sn, qs, ks);

    attn_mma<<<dim3(NTOK / 128, NHEAD), 256>>>(bq, bk, bv, bo);

    sgemm256<<<gg, 256>>>(bo, Wo, out, NTOK, HID, HID);
}